// round 11
// baseline (speedup 1.0000x reference)
#include <cuda_runtime.h>
#include <cuda_fp16.h>
#include <math.h>
#include <cstdint>

// Problem constants (fixed by the dataset)
#define S_LEN 2048
#define D_MODEL 1280
#define N_QKV 3840
#define N_HEADS 16
#define HEAD_DIM 80
#define SEG_LEN 256

// Global scratch
__device__ __half g_xh[S_LEN * D_MODEL];
__device__ __half g_wh[N_QKV * D_MODEL];
// [head][s][d] fp16
__device__ __half g_qh[N_HEADS * S_LEN * HEAD_DIM];
__device__ __half g_ql[N_HEADS * S_LEN * HEAD_DIM];
__device__ __half g_kh[N_HEADS * S_LEN * HEAD_DIM];
__device__ __half g_vh[N_HEADS * S_LEN * HEAD_DIM];

// ---------------------------------------------------------------------------
// Helpers
// ---------------------------------------------------------------------------
__device__ __forceinline__ uint32_t smem_u32(const void* p) {
    uint32_t a;
    asm("{ .reg .u64 t; cvta.to.shared.u64 t, %1; cvt.u32.u64 %0, t; }"
        : "=r"(a) : "l"(p));
    return a;
}
__device__ __forceinline__ void ldsm_x4(uint32_t* r, uint32_t addr) {
    asm volatile("ldmatrix.sync.aligned.m8n8.x4.shared.b16 {%0,%1,%2,%3}, [%4];"
                 : "=r"(r[0]), "=r"(r[1]), "=r"(r[2]), "=r"(r[3]) : "r"(addr));
}
__device__ __forceinline__ void ldsm_x2(uint32_t* r, uint32_t addr) {
    asm volatile("ldmatrix.sync.aligned.m8n8.x2.shared.b16 {%0,%1}, [%2];"
                 : "=r"(r[0]), "=r"(r[1]) : "r"(addr));
}
__device__ __forceinline__ void ldsm_x2_trans(uint32_t* r, uint32_t addr) {
    asm volatile("ldmatrix.sync.aligned.m8n8.x2.trans.shared.b16 {%0,%1}, [%2];"
                 : "=r"(r[0]), "=r"(r[1]) : "r"(addr));
}
__device__ __forceinline__ void mma_f16(float* c, const uint32_t* a, const uint32_t* b) {
    asm volatile(
        "mma.sync.aligned.m16n8k16.row.col.f32.f16.f16.f32 "
        "{%0,%1,%2,%3}, {%4,%5,%6,%7}, {%8,%9}, {%0,%1,%2,%3};"
        : "+f"(c[0]), "+f"(c[1]), "+f"(c[2]), "+f"(c[3])
        : "r"(a[0]), "r"(a[1]), "r"(a[2]), "r"(a[3]), "r"(b[0]), "r"(b[1]));
}
__device__ __forceinline__ void cp16(uint32_t dst, const void* src) {
    asm volatile("cp.async.ca.shared.global [%0], [%1], 16;" :: "r"(dst), "l"(src));
}
#define CP_COMMIT() asm volatile("cp.async.commit_group;" ::: "memory")
#define CP_WAIT2() asm volatile("cp.async.wait_group 2;" ::: "memory")
#define CP_WAIT1() asm volatile("cp.async.wait_group 1;" ::: "memory")
#define CP_WAIT0() asm volatile("cp.async.wait_group 0;" ::: "memory")

__device__ __forceinline__ void split2h(float v, __half& h, __half& l) {
    h = __float2half(v);
    l = __float2half(v - __half2float(h));
}

// ---------------------------------------------------------------------------
// Kernel 0: round x and W to fp16. 8 floats per thread, 16B stores.
// ---------------------------------------------------------------------------
#define NX8 (S_LEN * D_MODEL / 8)   // 327680
#define NW8 (N_QKV * D_MODEL / 8)   // 614400

__global__ __launch_bounds__(256) void split_kernel(
    const float* __restrict__ x, const float* __restrict__ w)
{
    int i = blockIdx.x * blockDim.x + threadIdx.x;
    if (i >= NX8 + NW8) return;
    const float4* src;
    uint4* dst;
    int off;
    if (i < NX8) { src = (const float4*)x; dst = (uint4*)g_xh; off = i; }
    else { src = (const float4*)w; dst = (uint4*)g_wh; off = i - NX8; }
    float4 v0 = src[2 * off];
    float4 v1 = src[2 * off + 1];
    __half2 p0 = __floats2half2_rn(v0.x, v0.y);
    __half2 p1 = __floats2half2_rn(v0.z, v0.w);
    __half2 p2 = __floats2half2_rn(v1.x, v1.y);
    __half2 p3 = __floats2half2_rn(v1.z, v1.w);
    uint4 H;
    H.x = *(uint32_t*)&p0; H.y = *(uint32_t*)&p1;
    H.z = *(uint32_t*)&p2; H.w = *(uint32_t*)&p3;
    dst[off] = H;
}

// ---------------------------------------------------------------------------
// Kernel 1: QKV GEMM, uniform fp16 1-pass, BM=128 x BN=128 x BK=32,
// 256 threads / 8 warps (2x4), 3-stage cp.async pipeline, occ 2.
// Epilogue writes Q (scaled, split hi/lo from fp32 acc), K, V fp16 [h][s][d].
// ---------------------------------------------------------------------------
#define GBM 128
#define GBN 128
#define GBK 32
#define NCHUNK (D_MODEL / GBK)   // 40
#define AST 40                   // smem row stride (halfs) = 80 B, conflict-free
#define OFF_A 0
#define OFF_B (GBM * AST * 2)            // 10240
#define STAGE_BYTES (OFF_B + GBN * AST * 2)  // 20480
#define NSTAGE 3
#define GEMM_SMEM (NSTAGE * STAGE_BYTES)     // 61440

__global__ __launch_bounds__(256, 2) void qkv_gemm_mma(
    const float* __restrict__ bias)
{
    extern __shared__ char smem[];
    const uint32_t sb = smem_u32(smem);

    const int tid = threadIdx.x;
    const int wid = tid >> 5;
    const int lane = tid & 31;
    const int wm = wid >> 2;        // 0..1 -> 64 rows each
    const int wn = wid & 3;         // 0..3 -> 32 cols each
    const int bn = blockIdx.x * GBN;
    const int bm = blockIdx.y * GBM;

    float acc[4][4][4];
#pragma unroll
    for (int i = 0; i < 4; i++)
#pragma unroll
        for (int j = 0; j < 4; j++)
#pragma unroll
            for (int k = 0; k < 4; k++) acc[i][j][k] = 0.0f;

    const int lr = lane & 7;
    const int lsub = lane >> 3;
    const int a_row_off = (lsub & 1) * 8 + lr;
    const int a_k_off = (lsub >> 1) * 8;
    const int b_k_off = (lsub & 1) * 8;

    // per-stage loader: A 512 chunks + B 512 chunks over 256 threads = 4 cp16
    auto load_stage = [&](int c, int st) {
        uint32_t dbase = sb + st * STAGE_BYTES;
        size_t k0 = (size_t)c * GBK;
#pragma unroll
        for (int i = 0; i < 2; i++) {
            int id = i * 256 + tid;
            int row = id >> 2, ch = id & 3;
            uint32_t d = dbase + (uint32_t)(row * AST + ch * 8) * 2;
            size_t so = k0 + ch * 8;
            cp16(d + OFF_A, g_xh + (size_t)(bm + row) * D_MODEL + so);
            cp16(d + OFF_B, g_wh + (size_t)(bn + row) * D_MODEL + so);
        }
        CP_COMMIT();
    };

    load_stage(0, 0);
    load_stage(1, 1);

    for (int c = 0; c < NCHUNK; c++) {
        if (c + 2 < NCHUNK) {
            load_stage(c + 2, (c + 2) % NSTAGE);
            CP_WAIT2();
        } else if (c + 1 < NCHUNK) {
            CP_WAIT1();
        } else {
            CP_WAIT0();
        }
        __syncthreads();

        const uint32_t sA = sb + (c % NSTAGE) * STAGE_BYTES + OFF_A;
        const uint32_t sB = sb + (c % NSTAGE) * STAGE_BYTES + OFF_B;

#pragma unroll
        for (int ks = 0; ks < 2; ks++) {
            uint32_t ah[4][4];
#pragma unroll
            for (int mb = 0; mb < 4; mb++) {
                uint32_t off = (uint32_t)((wm * 64 + mb * 16 + a_row_off) * AST
                                          + ks * 16 + a_k_off) * 2;
                ldsm_x4(ah[mb], sA + off);
            }
#pragma unroll
            for (int nb = 0; nb < 4; nb++) {
                uint32_t bh[2];
                uint32_t off = (uint32_t)((wn * 32 + nb * 8 + lr) * AST
                                          + ks * 16 + b_k_off) * 2;
                ldsm_x2(bh, sB + off);
#pragma unroll
                for (int mb = 0; mb < 4; mb++)
                    mma_f16(acc[mb][nb], ah[mb], bh);
            }
        }
        __syncthreads();
    }

    // epilogue: bias add, route to Q(scaled, split)/K/V fp16 [h][s][d]
    const float scale = 0.111803398874989485f;  // 1/sqrt(80)
    const int g = lane >> 2;
    const int cc = lane & 3;
#pragma unroll
    for (int nb = 0; nb < 4; nb++) {
        int col = bn + wn * 32 + nb * 8 + cc * 2;
        int sec = col / D_MODEL;          // 0=q 1=k 2=v
        int f = col - sec * D_MODEL;
        int h = f / HEAD_DIM;
        int d = f - h * HEAD_DIM;
        float2 bv = *(const float2*)&bias[col];
        size_t hb = (size_t)h * S_LEN * HEAD_DIM + d;
#pragma unroll
        for (int mb = 0; mb < 4; mb++) {
#pragma unroll
            for (int rr = 0; rr < 2; rr++) {
                int row = bm + wm * 64 + mb * 16 + g + rr * 8;
                float v0 = acc[mb][nb][rr * 2 + 0] + bv.x;
                float v1 = acc[mb][nb][rr * 2 + 1] + bv.y;
                size_t idx = hb + (size_t)row * HEAD_DIM;
                if (sec == 0) {
                    v0 *= scale; v1 *= scale;
                    __half h0, l0h, h1, l1h;
                    split2h(v0, h0, l0h);
                    split2h(v1, h1, l1h);
                    *(__half2*)&g_qh[idx] = __halves2half2(h0, h1);
                    *(__half2*)&g_ql[idx] = __halves2half2(l0h, l1h);
                } else if (sec == 1) {
                    *(__half2*)&g_kh[idx] = __floats2half2_rn(v0, v1);
                } else {
                    *(__half2*)&g_vh[idx] = __floats2half2_rn(v0, v1);
                }
            }
        }
    }
}

// ---------------------------------------------------------------------------
// Kernel 2: block-diagonal flash attention, fp16, 512 threads / 16 warps.
// Warps 0-7 own Q rows [0,128), warps 8-15 own [128,256).
// QK^T: 2-pass (Q split); PV: 1-pass. V via ldmatrix.trans.
// ---------------------------------------------------------------------------
#define AK 88    // row stride (halfs): 176 B, conflict-free

#define OFF_QH 0
#define OFF_QL (OFF_QH + 256 * AK * 2)    // 45056
#define OFF_KH (OFF_QL + 256 * AK * 2)    // 90112
#define OFF_VH (OFF_KH + 256 * AK * 2)    // 135168
#define ATTN_SMEM (OFF_VH + 256 * AK * 2) // 180224

__global__ __launch_bounds__(512, 1) void attn_mma(
    const int* __restrict__ cu_seqlens,
    float* __restrict__ out)
{
    extern __shared__ char smem[];
    const uint32_t sb = smem_u32(smem);

    const int seg = blockIdx.x;
    const int h = blockIdx.y;
    const int s0 = cu_seqlens[seg];

    const int tid = threadIdx.x;
    const int wid = tid >> 5;
    const int lane = tid & 31;
    const int qt = wid >> 3;        // 0 or 1: which 128-row Q tile
    const int w8 = wid & 7;         // warp within tile
    const int lr = lane & 7;
    const int lsub = lane >> 3;
    const int a_row_off = (lsub & 1) * 8 + lr;
    const int a_k_off = (lsub >> 1) * 8;
    const int b_k_off = (lsub & 1) * 8;
    const int g = lane >> 2;
    const int qc = lane & 3;
    const int mr = w8 * 16;

    // ---- cp.async all tiles: thread = (row, half-row); 5 chunks per array ----
    {
        const int row = tid >> 1;
        const int half = tid & 1;
        const size_t hbase = (size_t)h * S_LEN * HEAD_DIM + (size_t)s0 * HEAD_DIM
                             + (size_t)row * HEAD_DIM + half * 40;
        const __half* srcq = g_qh + hbase;
        const __half* srcl = g_ql + hbase;
        const __half* srck = g_kh + hbase;
        const __half* srcv = g_vh + hbase;
        uint32_t drow = sb + (uint32_t)(row * AK + half * 40) * 2;
#pragma unroll
        for (int c = 0; c < 5; c++) {
            cp16(drow + OFF_QH + c * 16, srcq + c * 8);
            cp16(drow + OFF_QL + c * 16, srcl + c * 8);
            cp16(drow + OFF_KH + c * 16, srck + c * 8);
            cp16(drow + OFF_VH + c * 16, srcv + c * 8);
        }
        CP_COMMIT();
    }
    CP_WAIT0();
    __syncthreads();

    const uint32_t kh_base = sb + OFF_KH + (uint32_t)(lr * AK + b_k_off) * 2;
    const uint32_t vh_base = sb + OFF_VH + (uint32_t)(a_row_off * AK) * 2;
    const uint32_t qh_base = sb + OFF_QH
        + (uint32_t)((qt * 128 + mr + a_row_off) * AK + a_k_off) * 2;
    const uint32_t ql_base = sb + OFF_QL
        + (uint32_t)((qt * 128 + mr + a_row_off) * AK + a_k_off) * 2;

    float oacc[10][4];
#pragma unroll
    for (int vb = 0; vb < 10; vb++)
#pragma unroll
        for (int k = 0; k < 4; k++) oacc[vb][k] = 0.0f;
    float m0 = -1e30f, m1 = -1e30f, l0 = 0.0f, l1 = 0.0f;

    for (int kt = 0; kt < 4; kt++) {
        // ---- S = Q K^T on this 64-wide KV tile (2-pass) ----
        float sacc[8][4];
#pragma unroll
        for (int nb = 0; nb < 8; nb++)
#pragma unroll
            for (int k = 0; k < 4; k++) sacc[nb][k] = 0.0f;

#pragma unroll
        for (int kb = 0; kb < 5; kb++) {
            uint32_t ah[4], al[4];
            ldsm_x4(ah, qh_base + kb * 32);
            ldsm_x4(al, ql_base + kb * 32);
#pragma unroll
            for (int nb = 0; nb < 8; nb++) {
                uint32_t bh[2];
                uint32_t ko = (uint32_t)((kt * 64 + nb * 8) * AK + kb * 16) * 2;
                ldsm_x2(bh, kh_base + ko);
                mma_f16(sacc[nb], ah, bh);
                mma_f16(sacc[nb], al, bh);
            }
        }

        // ---- online softmax ----
        float t0 = -1e30f, t1 = -1e30f;
#pragma unroll
        for (int nb = 0; nb < 8; nb++) {
            t0 = fmaxf(t0, fmaxf(sacc[nb][0], sacc[nb][1]));
            t1 = fmaxf(t1, fmaxf(sacc[nb][2], sacc[nb][3]));
        }
        t0 = fmaxf(t0, __shfl_xor_sync(0xFFFFFFFFu, t0, 1));
        t0 = fmaxf(t0, __shfl_xor_sync(0xFFFFFFFFu, t0, 2));
        t1 = fmaxf(t1, __shfl_xor_sync(0xFFFFFFFFu, t1, 1));
        t1 = fmaxf(t1, __shfl_xor_sync(0xFFFFFFFFu, t1, 2));

        float nm0 = fmaxf(m0, t0);
        float nm1 = fmaxf(m1, t1);
        float corr0 = __expf(m0 - nm0);
        float corr1 = __expf(m1 - nm1);
        m0 = nm0; m1 = nm1;
        l0 *= corr0; l1 *= corr1;
#pragma unroll
        for (int vb = 0; vb < 10; vb++) {
            oacc[vb][0] *= corr0; oacc[vb][1] *= corr0;
            oacc[vb][2] *= corr1; oacc[vb][3] *= corr1;
        }

        uint32_t ph0[8], ph1[8];
#pragma unroll
        for (int nb = 0; nb < 8; nb++) {
            float p0 = __expf(sacc[nb][0] - m0);
            float p1 = __expf(sacc[nb][1] - m0);
            float p2 = __expf(sacc[nb][2] - m1);
            float p3 = __expf(sacc[nb][3] - m1);
            l0 += p0 + p1;
            l1 += p2 + p3;
            __half2 a = __floats2half2_rn(p0, p1);
            __half2 b = __floats2half2_rn(p2, p3);
            ph0[nb] = *(uint32_t*)&a;
            ph1[nb] = *(uint32_t*)&b;
        }

        // ---- O += P V (1-pass, V via ldmatrix.trans) ----
#pragma unroll
        for (int kc = 0; kc < 4; kc++) {
            uint32_t aH[4] = { ph0[2 * kc], ph1[2 * kc], ph0[2 * kc + 1], ph1[2 * kc + 1] };
            uint32_t vrow = vh_base + (uint32_t)((kt * 64 + kc * 16) * AK) * 2;
#pragma unroll
            for (int vb = 0; vb < 10; vb++) {
                uint32_t bvh[2];
                ldsm_x2_trans(bvh, vrow + vb * 16);
                mma_f16(oacc[vb], aH, bvh);
            }
        }
    }

    // ---- finalize ----
    l0 += __shfl_xor_sync(0xFFFFFFFFu, l0, 1);
    l0 += __shfl_xor_sync(0xFFFFFFFFu, l0, 2);
    l1 += __shfl_xor_sync(0xFFFFFFFFu, l1, 1);
    l1 += __shfl_xor_sync(0xFFFFFFFFu, l1, 2);
    float inv0 = 1.0f / l0;
    float inv1 = 1.0f / l1;

    int row0 = s0 + qt * 128 + mr + g;
    float* op0 = &out[(size_t)row0 * (N_HEADS * HEAD_DIM) + h * HEAD_DIM + qc * 2];
    float* op1 = &out[(size_t)(row0 + 8) * (N_HEADS * HEAD_DIM) + h * HEAD_DIM + qc * 2];
#pragma unroll
    for (int vb = 0; vb < 10; vb++) {
        float2 a, b;
        a.x = oacc[vb][0] * inv0; a.y = oacc[vb][1] * inv0;
        b.x = oacc[vb][2] * inv1; b.y = oacc[vb][3] * inv1;
        *(float2*)&op0[vb * 8] = a;
        *(float2*)&op1[vb * 8] = b;
    }
}

// ---------------------------------------------------------------------------
// Launcher
// ---------------------------------------------------------------------------
extern "C" void kernel_launch(void* const* d_in, const int* in_sizes, int n_in,
                              void* d_out, int out_size)
{
    const float* x    = (const float*)d_in[0];
    const int*   cu   = (const int*)d_in[1];
    const float* Wqkv = (const float*)d_in[2];
    const float* bqkv = (const float*)d_in[3];
    float* out = (float*)d_out;

    const int nseg = in_sizes[1] - 1;

    // 0) round x, W to fp16
    split_kernel<<<(NX8 + NW8 + 255) / 256, 256>>>(x, Wqkv);

    // 1) QKV projection: uniform 1-pass fp16, 3-stage pipeline, occ 2
    cudaFuncSetAttribute(qkv_gemm_mma,
                         cudaFuncAttributeMaxDynamicSharedMemorySize, GEMM_SMEM);
    dim3 g1(N_QKV / GBN, S_LEN / GBM);   // 30 x 16
    qkv_gemm_mma<<<g1, 256, GEMM_SMEM>>>(bqkv);

    // 2) block-diagonal flash attention (512 threads, 16 warps)
    cudaFuncSetAttribute(attn_mma,
                         cudaFuncAttributeMaxDynamicSharedMemorySize, ATTN_SMEM);
    dim3 g2(nseg, N_HEADS);
    attn_mma<<<g2, 512, ATTN_SMEM>>>(cu, out);
}

// round 12
// speedup vs baseline: 1.4909x; 1.4909x over previous
#include <cuda_runtime.h>
#include <cuda_fp16.h>
#include <math.h>
#include <cstdint>

// Problem constants (fixed by the dataset)
#define S_LEN 2048
#define D_MODEL 1280
#define N_QKV 3840
#define N_HEADS 16
#define HEAD_DIM 80
#define SEG_LEN 256

// Global scratch
__device__ __half g_xh[S_LEN * D_MODEL];
__device__ __half g_wh[N_QKV * D_MODEL];
// [head][s][d] fp16
__device__ __half g_qh[N_HEADS * S_LEN * HEAD_DIM];
__device__ __half g_ql[N_HEADS * S_LEN * HEAD_DIM];
__device__ __half g_kh[N_HEADS * S_LEN * HEAD_DIM];
__device__ __half g_vh[N_HEADS * S_LEN * HEAD_DIM];

// ---------------------------------------------------------------------------
// Helpers
// ---------------------------------------------------------------------------
__device__ __forceinline__ uint32_t smem_u32(const void* p) {
    uint32_t a;
    asm("{ .reg .u64 t; cvta.to.shared.u64 t, %1; cvt.u32.u64 %0, t; }"
        : "=r"(a) : "l"(p));
    return a;
}
__device__ __forceinline__ void ldsm_x4(uint32_t* r, uint32_t addr) {
    asm volatile("ldmatrix.sync.aligned.m8n8.x4.shared.b16 {%0,%1,%2,%3}, [%4];"
                 : "=r"(r[0]), "=r"(r[1]), "=r"(r[2]), "=r"(r[3]) : "r"(addr));
}
__device__ __forceinline__ void ldsm_x2(uint32_t* r, uint32_t addr) {
    asm volatile("ldmatrix.sync.aligned.m8n8.x2.shared.b16 {%0,%1}, [%2];"
                 : "=r"(r[0]), "=r"(r[1]) : "r"(addr));
}
__device__ __forceinline__ void ldsm_x2_trans(uint32_t* r, uint32_t addr) {
    asm volatile("ldmatrix.sync.aligned.m8n8.x2.trans.shared.b16 {%0,%1}, [%2];"
                 : "=r"(r[0]), "=r"(r[1]) : "r"(addr));
}
__device__ __forceinline__ void mma_f16(float* c, const uint32_t* a, const uint32_t* b) {
    asm volatile(
        "mma.sync.aligned.m16n8k16.row.col.f32.f16.f16.f32 "
        "{%0,%1,%2,%3}, {%4,%5,%6,%7}, {%8,%9}, {%0,%1,%2,%3};"
        : "+f"(c[0]), "+f"(c[1]), "+f"(c[2]), "+f"(c[3])
        : "r"(a[0]), "r"(a[1]), "r"(a[2]), "r"(a[3]), "r"(b[0]), "r"(b[1]));
}
__device__ __forceinline__ void cp16(uint32_t dst, const void* src) {
    asm volatile("cp.async.ca.shared.global [%0], [%1], 16;" :: "r"(dst), "l"(src));
}
#define CP_COMMIT() asm volatile("cp.async.commit_group;" ::: "memory")
#define CP_WAIT1() asm volatile("cp.async.wait_group 1;" ::: "memory")
#define CP_WAIT0() asm volatile("cp.async.wait_group 0;" ::: "memory")

__device__ __forceinline__ void split2h(float v, __half& h, __half& l) {
    h = __float2half(v);
    l = __float2half(v - __half2float(h));
}

// ---------------------------------------------------------------------------
// Kernel 0: round x and W to fp16. 8 floats per thread, 16B stores.
// ---------------------------------------------------------------------------
#define NX8 (S_LEN * D_MODEL / 8)   // 327680
#define NW8 (N_QKV * D_MODEL / 8)   // 614400

__global__ __launch_bounds__(256) void split_kernel(
    const float* __restrict__ x, const float* __restrict__ w)
{
    int i = blockIdx.x * blockDim.x + threadIdx.x;
    if (i >= NX8 + NW8) return;
    const float4* src;
    uint4* dst;
    int off;
    if (i < NX8) { src = (const float4*)x; dst = (uint4*)g_xh; off = i; }
    else { src = (const float4*)w; dst = (uint4*)g_wh; off = i - NX8; }
    float4 v0 = src[2 * off];
    float4 v1 = src[2 * off + 1];
    __half2 p0 = __floats2half2_rn(v0.x, v0.y);
    __half2 p1 = __floats2half2_rn(v0.z, v0.w);
    __half2 p2 = __floats2half2_rn(v1.x, v1.y);
    __half2 p3 = __floats2half2_rn(v1.z, v1.w);
    uint4 H;
    H.x = *(uint32_t*)&p0; H.y = *(uint32_t*)&p1;
    H.z = *(uint32_t*)&p2; H.w = *(uint32_t*)&p3;
    dst[off] = H;
}

// ---------------------------------------------------------------------------
// Kernel 1: QKV GEMM, uniform fp16 1-pass, BM=128 x BN=128 x BK=32,
// 256 threads / 8 warps (2x4), 2-stage cp.async pipeline (R8 structure), occ 2.
// Epilogue writes Q (scaled, split hi/lo from fp32 acc), K, V fp16 [h][s][d].
// ---------------------------------------------------------------------------
#define GBM 128
#define GBN 128
#define GBK 32
#define NCHUNK (D_MODEL / GBK)   // 40
#define AST 40                   // smem row stride (halfs) = 80 B, conflict-free
#define OFF_A 0
#define OFF_B (GBM * AST * 2)            // 10240
#define STAGE_BYTES (OFF_B + GBN * AST * 2)  // 20480
#define GEMM_SMEM (2 * STAGE_BYTES)          // 40960

__global__ __launch_bounds__(256, 2) void qkv_gemm_mma(
    const float* __restrict__ bias)
{
    extern __shared__ char smem[];
    const uint32_t sb = smem_u32(smem);

    const int tid = threadIdx.x;
    const int wid = tid >> 5;
    const int lane = tid & 31;
    const int wm = wid >> 2;        // 0..1 -> 64 rows each
    const int wn = wid & 3;         // 0..3 -> 32 cols each
    const int bn = blockIdx.x * GBN;
    const int bm = blockIdx.y * GBM;

    float acc[4][4][4];
#pragma unroll
    for (int i = 0; i < 4; i++)
#pragma unroll
        for (int j = 0; j < 4; j++)
#pragma unroll
            for (int k = 0; k < 4; k++) acc[i][j][k] = 0.0f;

    const int lr = lane & 7;
    const int lsub = lane >> 3;
    const int a_row_off = (lsub & 1) * 8 + lr;
    const int a_k_off = (lsub >> 1) * 8;
    const int b_k_off = (lsub & 1) * 8;

    auto load_stage = [&](int c, int st) {
        uint32_t dbase = sb + st * STAGE_BYTES;
        size_t k0 = (size_t)c * GBK;
#pragma unroll
        for (int i = 0; i < 2; i++) {
            int id = i * 256 + tid;
            int row = id >> 2, ch = id & 3;
            uint32_t d = dbase + (uint32_t)(row * AST + ch * 8) * 2;
            size_t so = k0 + ch * 8;
            cp16(d + OFF_A, g_xh + (size_t)(bm + row) * D_MODEL + so);
            cp16(d + OFF_B, g_wh + (size_t)(bn + row) * D_MODEL + so);
        }
        CP_COMMIT();
    };

    load_stage(0, 0);

    for (int c = 0; c < NCHUNK; c++) {
        const int cur = c & 1;
        if (c + 1 < NCHUNK) {
            load_stage(c + 1, cur ^ 1);
            CP_WAIT1();
        } else {
            CP_WAIT0();
        }
        __syncthreads();

        const uint32_t sA = sb + cur * STAGE_BYTES + OFF_A;
        const uint32_t sB = sb + cur * STAGE_BYTES + OFF_B;

#pragma unroll
        for (int ks = 0; ks < 2; ks++) {
            uint32_t ah[4][4];
#pragma unroll
            for (int mb = 0; mb < 4; mb++) {
                uint32_t off = (uint32_t)((wm * 64 + mb * 16 + a_row_off) * AST
                                          + ks * 16 + a_k_off) * 2;
                ldsm_x4(ah[mb], sA + off);
            }
#pragma unroll
            for (int nb = 0; nb < 4; nb++) {
                uint32_t bh[2];
                uint32_t off = (uint32_t)((wn * 32 + nb * 8 + lr) * AST
                                          + ks * 16 + b_k_off) * 2;
                ldsm_x2(bh, sB + off);
#pragma unroll
                for (int mb = 0; mb < 4; mb++)
                    mma_f16(acc[mb][nb], ah[mb], bh);
            }
        }
        __syncthreads();
    }

    // epilogue: bias add, route to Q(scaled, split)/K/V fp16 [h][s][d]
    const float scale = 0.111803398874989485f;  // 1/sqrt(80)
    const int g = lane >> 2;
    const int cc = lane & 3;
#pragma unroll
    for (int nb = 0; nb < 4; nb++) {
        int col = bn + wn * 32 + nb * 8 + cc * 2;
        int sec = col / D_MODEL;          // 0=q 1=k 2=v
        int f = col - sec * D_MODEL;
        int h = f / HEAD_DIM;
        int d = f - h * HEAD_DIM;
        float2 bv = *(const float2*)&bias[col];
        size_t hb = (size_t)h * S_LEN * HEAD_DIM + d;
#pragma unroll
        for (int mb = 0; mb < 4; mb++) {
#pragma unroll
            for (int rr = 0; rr < 2; rr++) {
                int row = bm + wm * 64 + mb * 16 + g + rr * 8;
                float v0 = acc[mb][nb][rr * 2 + 0] + bv.x;
                float v1 = acc[mb][nb][rr * 2 + 1] + bv.y;
                size_t idx = hb + (size_t)row * HEAD_DIM;
                if (sec == 0) {
                    v0 *= scale; v1 *= scale;
                    __half h0, l0h, h1, l1h;
                    split2h(v0, h0, l0h);
                    split2h(v1, h1, l1h);
                    *(__half2*)&g_qh[idx] = __halves2half2(h0, h1);
                    *(__half2*)&g_ql[idx] = __halves2half2(l0h, l1h);
                } else if (sec == 1) {
                    *(__half2*)&g_kh[idx] = __floats2half2_rn(v0, v1);
                } else {
                    *(__half2*)&g_vh[idx] = __floats2half2_rn(v0, v1);
                }
            }
        }
    }
}

// ---------------------------------------------------------------------------
// Kernel 2: block-diagonal flash attention, fp16, 512 threads / 16 warps.
// Warps 0-7 own Q rows [0,128), warps 8-15 own [128,256).
// QK^T: 2-pass (Q split); PV: 1-pass. V via ldmatrix.trans.  (unchanged R8)
// ---------------------------------------------------------------------------
#define AK 88    // row stride (halfs): 176 B, conflict-free

#define OFF_QH 0
#define OFF_QL (OFF_QH + 256 * AK * 2)    // 45056
#define OFF_KH (OFF_QL + 256 * AK * 2)    // 90112
#define OFF_VH (OFF_KH + 256 * AK * 2)    // 135168
#define ATTN_SMEM (OFF_VH + 256 * AK * 2) // 180224

__global__ __launch_bounds__(512, 1) void attn_mma(
    const int* __restrict__ cu_seqlens,
    float* __restrict__ out)
{
    extern __shared__ char smem[];
    const uint32_t sb = smem_u32(smem);

    const int seg = blockIdx.x;
    const int h = blockIdx.y;
    const int s0 = cu_seqlens[seg];

    const int tid = threadIdx.x;
    const int wid = tid >> 5;
    const int lane = tid & 31;
    const int qt = wid >> 3;        // 0 or 1: which 128-row Q tile
    const int w8 = wid & 7;         // warp within tile
    const int lr = lane & 7;
    const int lsub = lane >> 3;
    const int a_row_off = (lsub & 1) * 8 + lr;
    const int a_k_off = (lsub >> 1) * 8;
    const int b_k_off = (lsub & 1) * 8;
    const int g = lane >> 2;
    const int qc = lane & 3;
    const int mr = w8 * 16;

    // ---- cp.async all tiles: thread = (row, half-row); 5 chunks per array ----
    {
        const int row = tid >> 1;
        const int half = tid & 1;
        const size_t hbase = (size_t)h * S_LEN * HEAD_DIM + (size_t)s0 * HEAD_DIM
                             + (size_t)row * HEAD_DIM + half * 40;
        const __half* srcq = g_qh + hbase;
        const __half* srcl = g_ql + hbase;
        const __half* srck = g_kh + hbase;
        const __half* srcv = g_vh + hbase;
        uint32_t drow = sb + (uint32_t)(row * AK + half * 40) * 2;
#pragma unroll
        for (int c = 0; c < 5; c++) {
            cp16(drow + OFF_QH + c * 16, srcq + c * 8);
            cp16(drow + OFF_QL + c * 16, srcl + c * 8);
            cp16(drow + OFF_KH + c * 16, srck + c * 8);
            cp16(drow + OFF_VH + c * 16, srcv + c * 8);
        }
        CP_COMMIT();
    }
    CP_WAIT0();
    __syncthreads();

    const uint32_t kh_base = sb + OFF_KH + (uint32_t)(lr * AK + b_k_off) * 2;
    const uint32_t vh_base = sb + OFF_VH + (uint32_t)(a_row_off * AK) * 2;
    const uint32_t qh_base = sb + OFF_QH
        + (uint32_t)((qt * 128 + mr + a_row_off) * AK + a_k_off) * 2;
    const uint32_t ql_base = sb + OFF_QL
        + (uint32_t)((qt * 128 + mr + a_row_off) * AK + a_k_off) * 2;

    float oacc[10][4];
#pragma unroll
    for (int vb = 0; vb < 10; vb++)
#pragma unroll
        for (int k = 0; k < 4; k++) oacc[vb][k] = 0.0f;
    float m0 = -1e30f, m1 = -1e30f, l0 = 0.0f, l1 = 0.0f;

    for (int kt = 0; kt < 4; kt++) {
        // ---- S = Q K^T on this 64-wide KV tile (2-pass) ----
        float sacc[8][4];
#pragma unroll
        for (int nb = 0; nb < 8; nb++)
#pragma unroll
            for (int k = 0; k < 4; k++) sacc[nb][k] = 0.0f;

#pragma unroll
        for (int kb = 0; kb < 5; kb++) {
            uint32_t ah[4], al[4];
            ldsm_x4(ah, qh_base + kb * 32);
            ldsm_x4(al, ql_base + kb * 32);
#pragma unroll
            for (int nb = 0; nb < 8; nb++) {
                uint32_t bh[2];
                uint32_t ko = (uint32_t)((kt * 64 + nb * 8) * AK + kb * 16) * 2;
                ldsm_x2(bh, kh_base + ko);
                mma_f16(sacc[nb], ah, bh);
                mma_f16(sacc[nb], al, bh);
            }
        }

        // ---- online softmax ----
        float t0 = -1e30f, t1 = -1e30f;
#pragma unroll
        for (int nb = 0; nb < 8; nb++) {
            t0 = fmaxf(t0, fmaxf(sacc[nb][0], sacc[nb][1]));
            t1 = fmaxf(t1, fmaxf(sacc[nb][2], sacc[nb][3]));
        }
        t0 = fmaxf(t0, __shfl_xor_sync(0xFFFFFFFFu, t0, 1));
        t0 = fmaxf(t0, __shfl_xor_sync(0xFFFFFFFFu, t0, 2));
        t1 = fmaxf(t1, __shfl_xor_sync(0xFFFFFFFFu, t1, 1));
        t1 = fmaxf(t1, __shfl_xor_sync(0xFFFFFFFFu, t1, 2));

        float nm0 = fmaxf(m0, t0);
        float nm1 = fmaxf(m1, t1);
        float corr0 = __expf(m0 - nm0);
        float corr1 = __expf(m1 - nm1);
        m0 = nm0; m1 = nm1;
        l0 *= corr0; l1 *= corr1;
#pragma unroll
        for (int vb = 0; vb < 10; vb++) {
            oacc[vb][0] *= corr0; oacc[vb][1] *= corr0;
            oacc[vb][2] *= corr1; oacc[vb][3] *= corr1;
        }

        uint32_t ph0[8], ph1[8];
#pragma unroll
        for (int nb = 0; nb < 8; nb++) {
            float p0 = __expf(sacc[nb][0] - m0);
            float p1 = __expf(sacc[nb][1] - m0);
            float p2 = __expf(sacc[nb][2] - m1);
            float p3 = __expf(sacc[nb][3] - m1);
            l0 += p0 + p1;
            l1 += p2 + p3;
            __half2 a = __floats2half2_rn(p0, p1);
            __half2 b = __floats2half2_rn(p2, p3);
            ph0[nb] = *(uint32_t*)&a;
            ph1[nb] = *(uint32_t*)&b;
        }

        // ---- O += P V (1-pass, V via ldmatrix.trans) ----
#pragma unroll
        for (int kc = 0; kc < 4; kc++) {
            uint32_t aH[4] = { ph0[2 * kc], ph1[2 * kc], ph0[2 * kc + 1], ph1[2 * kc + 1] };
            uint32_t vrow = vh_base + (uint32_t)((kt * 64 + kc * 16) * AK) * 2;
#pragma unroll
            for (int vb = 0; vb < 10; vb++) {
                uint32_t bvh[2];
                ldsm_x2_trans(bvh, vrow + vb * 16);
                mma_f16(oacc[vb], aH, bvh);
            }
        }
    }

    // ---- finalize ----
    l0 += __shfl_xor_sync(0xFFFFFFFFu, l0, 1);
    l0 += __shfl_xor_sync(0xFFFFFFFFu, l0, 2);
    l1 += __shfl_xor_sync(0xFFFFFFFFu, l1, 1);
    l1 += __shfl_xor_sync(0xFFFFFFFFu, l1, 2);
    float inv0 = 1.0f / l0;
    float inv1 = 1.0f / l1;

    int row0 = s0 + qt * 128 + mr + g;
    float* op0 = &out[(size_t)row0 * (N_HEADS * HEAD_DIM) + h * HEAD_DIM + qc * 2];
    float* op1 = &out[(size_t)(row0 + 8) * (N_HEADS * HEAD_DIM) + h * HEAD_DIM + qc * 2];
#pragma unroll
    for (int vb = 0; vb < 10; vb++) {
        float2 a, b;
        a.x = oacc[vb][0] * inv0; a.y = oacc[vb][1] * inv0;
        b.x = oacc[vb][2] * inv1; b.y = oacc[vb][3] * inv1;
        *(float2*)&op0[vb * 8] = a;
        *(float2*)&op1[vb * 8] = b;
    }
}

// ---------------------------------------------------------------------------
// Launcher
// ---------------------------------------------------------------------------
extern "C" void kernel_launch(void* const* d_in, const int* in_sizes, int n_in,
                              void* d_out, int out_size)
{
    const float* x    = (const float*)d_in[0];
    const int*   cu   = (const int*)d_in[1];
    const float* Wqkv = (const float*)d_in[2];
    const float* bqkv = (const float*)d_in[3];
    float* out = (float*)d_out;

    const int nseg = in_sizes[1] - 1;

    // 0) round x, W to fp16
    split_kernel<<<(NX8 + NW8 + 255) / 256, 256>>>(x, Wqkv);

    // 1) QKV projection: uniform 1-pass fp16, 2-stage pipeline (R8 structure)
    cudaFuncSetAttribute(qkv_gemm_mma,
                         cudaFuncAttributeMaxDynamicSharedMemorySize, GEMM_SMEM);
    dim3 g1(N_QKV / GBN, S_LEN / GBM);   // 30 x 16
    qkv_gemm_mma<<<g1, 256, GEMM_SMEM>>>(bqkv);

    // 2) block-diagonal flash attention (512 threads, 16 warps)
    cudaFuncSetAttribute(attn_mma,
                         cudaFuncAttributeMaxDynamicSharedMemorySize, ATTN_SMEM);
    dim3 g2(nseg, N_HEADS);
    attn_mma<<<g2, 512, ATTN_SMEM>>>(cu, out);
}